// round 1
// baseline (speedup 1.0000x reference)
#include <cuda_runtime.h>
#include <math.h>

#define POOL 7
#define C 256
#define CQ (C / 4)          // 64 float4 per pixel

// Grid: one block per (b, n) ROI. Block: (64, 8) — x = channel quad, y = cell.
__global__ __launch_bounds__(512, 2)
void roi_align_kernel(const float* __restrict__ rois,
                      const int*   __restrict__ image_shape,
                      const float* __restrict__ p2,
                      const float* __restrict__ p3,
                      const float* __restrict__ p4,
                      const float* __restrict__ p5,
                      float* __restrict__ out,
                      int N)
{
    const int bn = blockIdx.x;          // 0 .. B*N-1
    const int b  = bn / N;

    // Load ROI (y1, x1, y2, x2), normalized.
    const float4 r = reinterpret_cast<const float4*>(rois)[bn];
    const float y1 = r.x, x1 = r.y, y2 = r.z, x2 = r.w;
    const float h = y2 - y1;
    const float w = x2 - x1;

    // Level selection: scale = sqrt(h*w) / (224 / sqrt(img_area))
    const float img_area = (float)(image_shape[0]) * (float)(image_shape[1]);
    const float scale = sqrtf(fmaxf(h * w, 1e-12f)) * (sqrtf(img_area) / 224.0f);
    int lvl = 4 + (int)rintf(log2f(scale));   // rintf = round-half-even, matches jnp.round
    lvl = min(max(lvl, 2), 5);

    const float* feat;
    int H;
    switch (lvl) {
        case 2:  feat = p2; H = 256; break;
        case 3:  feat = p3; H = 128; break;
        case 4:  feat = p4; H = 64;  break;
        default: feat = p5; H = 32;  break;
    }
    feat += (size_t)b * (size_t)H * (size_t)H * C;

    const float Hm1 = (float)(H - 1);
    const float Hm2 = (float)(H - 2);

    const int cq = threadIdx.x;                // channel quad 0..63
    float4* out_bn = reinterpret_cast<float4*>(out + (size_t)bn * (POOL * POOL * C));

    for (int cell = threadIdx.y; cell < POOL * POOL; cell += blockDim.y) {
        const int py = cell / POOL;
        const int px = cell - py * POOL;

        // ys/xs exactly as reference: (y1 + (py/6)*(y2-y1)) * (H-1)
        const float gy = (float)py / (float)(POOL - 1);
        const float gx = (float)px / (float)(POOL - 1);
        const float ysf = (y1 + gy * h) * Hm1;
        const float xsf = (x1 + gx * w) * Hm1;

        float y0f = fminf(fmaxf(floorf(ysf), 0.0f), Hm2);
        float x0f = fminf(fmaxf(floorf(xsf), 0.0f), Hm2);
        const int y0 = (int)y0f;
        const int x0 = (int)x0f;
        const float ty = fminf(fmaxf(ysf - y0f, 0.0f), 1.0f);
        const float tx = fminf(fmaxf(xsf - x0f, 0.0f), 1.0f);

        const float4* row0 = reinterpret_cast<const float4*>(
            feat + ((size_t)y0 * H + x0) * C);
        const float4* row1 = reinterpret_cast<const float4*>(
            feat + ((size_t)(y0 + 1) * H + x0) * C);

        // 4 coalesced 16B loads per thread (adjacent x pixels are contiguous).
        const float4 v00 = row0[cq];
        const float4 v01 = row0[cq + CQ];
        const float4 v10 = row1[cq];
        const float4 v11 = row1[cq + CQ];

        const float wty = 1.0f - ty;
        const float wtx = 1.0f - tx;

        float4 res;
        {
            float top, bot;
            top = v00.x * wtx + v01.x * tx;  bot = v10.x * wtx + v11.x * tx;
            res.x = top * wty + bot * ty;
            top = v00.y * wtx + v01.y * tx;  bot = v10.y * wtx + v11.y * tx;
            res.y = top * wty + bot * ty;
            top = v00.z * wtx + v01.z * tx;  bot = v10.z * wtx + v11.z * tx;
            res.z = top * wty + bot * ty;
            top = v00.w * wtx + v01.w * tx;  bot = v10.w * wtx + v11.w * tx;
            res.w = top * wty + bot * ty;
        }

        out_bn[cell * CQ + cq] = res;
    }
}

extern "C" void kernel_launch(void* const* d_in, const int* in_sizes, int n_in,
                              void* d_out, int out_size)
{
    const float* rois        = (const float*)d_in[0];
    const int*   image_shape = (const int*)  d_in[1];
    const float* p2          = (const float*)d_in[2];
    const float* p3          = (const float*)d_in[3];
    const float* p4          = (const float*)d_in[4];
    const float* p5          = (const float*)d_in[5];
    float*       out         = (float*)d_out;

    // Derive B, N from sizes: p2 is [B, 256, 256, 256], rois is [B, N, 4].
    const int B = in_sizes[2] / (256 * 256 * 256);
    const int N = in_sizes[0] / (4 * B);

    dim3 block(64, 8);
    dim3 grid(B * N);
    roi_align_kernel<<<grid, block>>>(rois, image_shape, p2, p3, p4, p5, out, N);
}

// round 2
// speedup vs baseline: 1.1430x; 1.1430x over previous
#include <cuda_runtime.h>
#include <math.h>

#define POOL 7
#define C 256
#define CQ (C / 4)          // 64 float4 per pixel

typedef unsigned long long u64;

// Packed 2xfp32 math (Blackwell f32x2 pipe) — PTX only, ptxas won't auto-fuse.
__device__ __forceinline__ u64 f32x2_mul(u64 a, u64 b) {
    u64 d; asm("mul.rn.f32x2 %0, %1, %2;" : "=l"(d) : "l"(a), "l"(b)); return d;
}
__device__ __forceinline__ u64 f32x2_fma(u64 a, u64 b, u64 c) {
    u64 d; asm("fma.rn.f32x2 %0, %1, %2, %3;" : "=l"(d) : "l"(a), "l"(b), "l"(c)); return d;
}
__device__ __forceinline__ u64 f32x2_pack(float v) {
    u64 d; asm("mov.b64 %0, {%1, %1};" : "=l"(d) : "f"(v)); return d;
}

// One packed bilinear lerp on a 2-float pair.
__device__ __forceinline__ u64 bilerp2(u64 v00, u64 v01, u64 v10, u64 v11,
                                       u64 wtx2, u64 tx2, u64 wty2, u64 ty2) {
    u64 top = f32x2_fma(v01, tx2, f32x2_mul(v00, wtx2));
    u64 bot = f32x2_fma(v11, tx2, f32x2_mul(v10, wtx2));
    return f32x2_fma(bot, ty2, f32x2_mul(top, wty2));
}

// Grid: one block per (b,n) ROI. Block (32, 8): x = lane (handles quads cq and cq+32), y = cell.
__global__ __launch_bounds__(256)
void roi_align_kernel(const float* __restrict__ rois,
                      const int*   __restrict__ image_shape,
                      const float* __restrict__ p2,
                      const float* __restrict__ p3,
                      const float* __restrict__ p4,
                      const float* __restrict__ p5,
                      float* __restrict__ out,
                      int N)
{
    const int bn = blockIdx.x;
    const int b  = bn / N;

    const float4 r = reinterpret_cast<const float4*>(rois)[bn];
    const float y1 = r.x, x1 = r.y, y2 = r.z, x2 = r.w;
    const float h = y2 - y1;
    const float w = x2 - x1;

    const float img_area = (float)(image_shape[0]) * (float)(image_shape[1]);
    const float scale = sqrtf(fmaxf(h * w, 1e-12f)) * (sqrtf(img_area) / 224.0f);
    int lvl = 4 + (int)rintf(log2f(scale));
    lvl = min(max(lvl, 2), 5);

    const float* feat;
    int H;
    switch (lvl) {
        case 2:  feat = p2; H = 256; break;
        case 3:  feat = p3; H = 128; break;
        case 4:  feat = p4; H = 64;  break;
        default: feat = p5; H = 32;  break;
    }
    feat += (size_t)b * (size_t)H * (size_t)H * C;

    const float Hm1 = (float)(H - 1);
    const float Hm2 = (float)(H - 2);

    const int lane = threadIdx.x;            // 0..31, handles quads lane and lane+32
    float4* out_bn = reinterpret_cast<float4*>(out + (size_t)bn * (POOL * POOL * C));

    for (int cell = threadIdx.y; cell < POOL * POOL; cell += 8) {
        const int py = cell / POOL;
        const int px = cell - py * POOL;

        const float gy = (float)py * (1.0f / (POOL - 1));
        const float gx = (float)px * (1.0f / (POOL - 1));
        const float ysf = (y1 + gy * h) * Hm1;
        const float xsf = (x1 + gx * w) * Hm1;

        const float y0f = fminf(fmaxf(floorf(ysf), 0.0f), Hm2);
        const float x0f = fminf(fmaxf(floorf(xsf), 0.0f), Hm2);
        const int y0 = (int)y0f;
        const int x0 = (int)x0f;
        const float ty = fminf(fmaxf(ysf - y0f, 0.0f), 1.0f);
        const float tx = fminf(fmaxf(xsf - x0f, 0.0f), 1.0f);

        const ulonglong2* row0 = reinterpret_cast<const ulonglong2*>(
            feat + ((size_t)y0 * H + x0) * C) + lane;
        const ulonglong2* row1 = reinterpret_cast<const ulonglong2*>(
            feat + ((size_t)(y0 + 1) * H + x0) * C) + lane;

        // 8 back-to-back LDG.128 (MLP=8), immediate offsets off two bases.
        const ulonglong2 a00 = row0[0];
        const ulonglong2 a01 = row0[CQ];
        const ulonglong2 a10 = row1[0];
        const ulonglong2 a11 = row1[CQ];
        const ulonglong2 b00 = row0[32];
        const ulonglong2 b01 = row0[CQ + 32];
        const ulonglong2 b10 = row1[32];
        const ulonglong2 b11 = row1[CQ + 32];

        const u64 wtx2 = f32x2_pack(1.0f - tx);
        const u64 tx2  = f32x2_pack(tx);
        const u64 wty2 = f32x2_pack(1.0f - ty);
        const u64 ty2  = f32x2_pack(ty);

        ulonglong2 ra, rb;
        ra.x = bilerp2(a00.x, a01.x, a10.x, a11.x, wtx2, tx2, wty2, ty2);
        ra.y = bilerp2(a00.y, a01.y, a10.y, a11.y, wtx2, tx2, wty2, ty2);
        rb.x = bilerp2(b00.x, b01.x, b10.x, b11.x, wtx2, tx2, wty2, ty2);
        rb.y = bilerp2(b00.y, b01.y, b10.y, b11.y, wtx2, tx2, wty2, ty2);

        // Streaming stores: write-once output, don't pollute L2 (keep features hot).
        float4* o = reinterpret_cast<float4*>(out_bn + (size_t)cell * CQ) + lane;
        __stcs(o,      *reinterpret_cast<float4*>(&ra));
        __stcs(o + 32, *reinterpret_cast<float4*>(&rb));
    }
}

extern "C" void kernel_launch(void* const* d_in, const int* in_sizes, int n_in,
                              void* d_out, int out_size)
{
    const float* rois        = (const float*)d_in[0];
    const int*   image_shape = (const int*)  d_in[1];
    const float* p2          = (const float*)d_in[2];
    const float* p3          = (const float*)d_in[3];
    const float* p4          = (const float*)d_in[4];
    const float* p5          = (const float*)d_in[5];
    float*       out         = (float*)d_out;

    const int B = in_sizes[2] / (256 * 256 * 256);
    const int N = in_sizes[0] / (4 * B);

    dim3 block(32, 8);
    dim3 grid(B * N);
    roi_align_kernel<<<grid, block>>>(rois, image_shape, p2, p3, p4, p5, out, N);
}